// round 2
// baseline (speedup 1.0000x reference)
#include <cuda_runtime.h>

#define C     62
#define FIN   512
#define FOUT  256
#define KCH   5
#define NCLS  2
#define BATCH 2048
#define REDN  (C*FIN)     // 31744
#define CFOUT (C*FOUT)    // 15872
#define NE    (C*C)       // 3844

// ---------------- scratch (device globals, no allocation) ----------------
__device__ float d_T[KCH*NE];                     // Chebyshev matrices T_k, row-major [c][i]
__device__ float d_G[NCLS*C*KCH*FOUT];            // [(n*62+i)*1280 + k*256 + f]
__device__ __align__(16) float d_Mf[REDN*NCLS];   // collapsed matrix, [(i*512+j)*2 + n]

// ---------------- 1) fused adjacency MLP + Laplacian + Chebyshev ----------------
__global__ void __launch_bounds__(1024) k_adjcheb(
        const float* __restrict__ coord, const float* __restrict__ w1,
        const float* __restrict__ b1, const float* __restrict__ w2,
        const float* __restrict__ b2) {
    __shared__ float Ls[NE];
    __shared__ float Ta[NE];
    __shared__ float Tb[NE];
    __shared__ float dis[C];
    int tid = threadIdx.x;   // 1024

    // --- adjacency MLP + threshold, straight into smem ---
    for (int e = tid; e < NE; e += 1024) {
        int c1 = e / C, c2 = e % C;
        const float* cd = coord + e*4;
        float d0 = cd[0], d1 = cd[1], d2 = cd[2], d3 = cd[3];
        float acc = b2[0];
        #pragma unroll 8
        for (int h = 0; h < 64; h++) {
            float t = d0*w1[h] + d1*w1[64+h] + d2*w1[128+h] + d3*w1[192+h] + b1[h];
            acc += fmaxf(t, 0.0f) * w2[h];
        }
        Ls[e] = (c1 != c2 && acc > 0.1f) ? acc : 0.0f;
    }
    __syncthreads();

    // --- degree + rsqrt ---
    if (tid < C) {
        float s = 0.0f;
        #pragma unroll
        for (int j = 0; j < C; j++) s += Ls[tid*C + j];
        dis[tid] = (s > 0.0f) ? (1.0f / sqrtf(s)) : 0.0f;
    }
    __syncthreads();

    // --- L = -D^-1/2 A D^-1/2 ; T0 = I, T1 = L ---
    for (int e = tid; e < NE; e += 1024) {
        int r = e / C, c = e % C;
        float L = -(dis[r] * Ls[e] * dis[c]);
        Ls[e] = L;
        Ta[e] = L;
        float t0 = (r == c) ? 1.0f : 0.0f;
        Tb[e] = t0;
        d_T[0*NE + e] = t0;
        d_T[1*NE + e] = L;
    }
    __syncthreads();

    // --- Tk = 2 L T_{k-1} - T_{k-2} ---
    for (int k = 2; k < KCH; k++) {
        float v[4];
        int cnt = 0;
        for (int e = tid; e < NE; e += 1024, cnt++) {
            int r = e / C, c = e % C;
            float s = 0.0f;
            #pragma unroll
            for (int j = 0; j < C; j++) s += Ls[r*C + j] * Ta[j*C + c];
            v[cnt] = 2.0f*s - Tb[e];
        }
        __syncthreads();
        cnt = 0;
        for (int e = tid; e < NE; e += 1024, cnt++) {
            Tb[e] = Ta[e];
            Ta[e] = v[cnt];
            d_T[k*NE + e] = v[cnt];
        }
        __syncthreads();
    }
}

// ---------------- 2) fused: G compute (blk<620) + Mf zero (620..681) + const/out init (682)
__global__ void __launch_bounds__(256) k_Gz(
        const float* __restrict__ fcw, const float* __restrict__ chebb,
        const float* __restrict__ convw, const float* __restrict__ convb,
        const float* __restrict__ fcb, float* __restrict__ out) {
    int blk = blockIdx.x;
    int tid = threadIdx.x;

    if (blk < 620) {
        // (n,i,k) constant per block, f = tid
        int g0 = blk*256;
        int k  = (g0 >> 8) % KCH;
        int ni = g0 / (KCH*FOUT);
        int i  = ni % C;
        int n  = ni / C;
        __shared__ float Ts[C];
        if (tid < C) Ts[tid] = d_T[k*NE + tid*C + i];
        __syncthreads();
        int f = tid;
        float acc = 0.0f;
        #pragma unroll
        for (int c = 0; c < C; c++)
            acc += Ts[c] * fcw[(c*FOUT + f)*NCLS + n];
        d_G[g0 + tid] = acc;
    } else if (blk < 682) {
        int idx = (blk - 620)*256 + tid;   // 15872 float4
        ((float4*)d_Mf)[idx] = make_float4(0.f, 0.f, 0.f, 0.f);
    } else {
        // const term + init out
        __shared__ float red[1024];
        __shared__ float cst[2];
        float s0 = 0.f, s1 = 0.f, t0 = 0.f, t1 = 0.f;
        for (int cf = tid; cf < CFOUT; cf += 256) {
            float w0 = fcw[cf*2], w1v = fcw[cf*2 + 1];
            float bb = chebb[cf & 255];
            s0 += w0; s1 += w1v; t0 += bb*w0; t1 += bb*w1v;
        }
        red[tid] = s0; red[256+tid] = s1; red[512+tid] = t0; red[768+tid] = t1;
        __syncthreads();
        for (int off = 128; off > 0; off >>= 1) {
            if (tid < off) {
                red[tid]     += red[tid+off];
                red[256+tid] += red[256+tid+off];
                red[512+tid] += red[512+tid+off];
                red[768+tid] += red[768+tid+off];
            }
            __syncthreads();
        }
        if (tid == 0) {
            float cw = convw[0], cb = convb[0];
            cst[0] = cw*red[512] + cb*red[0]   + fcb[0];
            cst[1] = cw*red[768] + cb*red[256] + fcb[1];
        }
        __syncthreads();
        float c0 = cst[0], c1 = cst[1];
        for (int b = tid; b < BATCH; b += 256) {
            out[b*2]     = c0;
            out[b*2 + 1] = c1;
        }
    }
}

// ---------------- 3) M[n,i,j] += conv_w * sum_{k,f} G[n,i,kf] * chebW[k,j,f] ----------
__global__ void __launch_bounds__(256) k_M(const float* __restrict__ chebW,
                                           const float* __restrict__ convw) {
    __shared__ float Gs[64*68];
    __shared__ float Ws[64*68];
    int tid = threadIdx.x;
    int kf0 = blockIdx.x * 64;
    int k   = kf0 >> 8;
    int f0  = kf0 & 255;
    int j0  = blockIdx.y * 64;
    int n   = blockIdx.z;

    {
        int cc = tid & 63;
        int r0 = tid >> 6;
        #pragma unroll
        for (int s = 0; s < 16; s++) {
            int r = r0 + s*4;
            float v = (r < C) ? d_G[(n*C + r)*(KCH*FOUT) + kf0 + cc] : 0.0f;
            Gs[cc*68 + r] = v;
        }
        #pragma unroll
        for (int s = 0; s < 16; s++) {
            int j = r0 + s*4;
            Ws[cc*68 + j] = chebW[k*(FIN*FOUT) + (j0 + j)*FOUT + f0 + cc];
        }
    }
    __syncthreads();

    int tx = tid & 15, ty = tid >> 4;
    int r4 = ty*4, j4 = tx*4;
    float acc[4][4] = {};
    #pragma unroll
    for (int kk = 0; kk < 64; kk++) {
        float4 g = *(const float4*)&Gs[kk*68 + r4];
        float4 w = *(const float4*)&Ws[kk*68 + j4];
        float gg[4] = {g.x, g.y, g.z, g.w};
        float ww[4] = {w.x, w.y, w.z, w.w};
        #pragma unroll
        for (int a = 0; a < 4; a++)
            #pragma unroll
            for (int b = 0; b < 4; b++)
                acc[a][b] += gg[a]*ww[b];
    }

    float cw = convw[0];
    #pragma unroll
    for (int a = 0; a < 4; a++) {
        int i = r4 + a;
        if (i >= C) continue;
        #pragma unroll
        for (int b = 0; b < 4; b++) {
            int j = j0 + j4 + b;
            atomicAdd(&d_Mf[(i*FIN + j)*NCLS + n], cw*acc[a][b]);
        }
    }
}

// ---------------- 4) main pass: final[b,n] += sum_idx x[b,idx]*M[idx,n] --------------
__global__ void __launch_bounds__(256) k_main(const float* __restrict__ x,
                                              float* __restrict__ out) {
    __shared__ __align__(16) float4 Ms4[1984];   // 31.7KB chunk of Mf
    int chunk = blockIdx.x & 7;
    int bg    = blockIdx.x >> 3;
    int idx0  = chunk * 3968;
    int tid   = threadIdx.x;

    const float4* Mf4 = (const float4*)(d_Mf + idx0*2);
    for (int t = tid; t < 1984; t += 256) Ms4[t] = Mf4[t];
    __syncthreads();

    int warp = tid >> 5, lane = tid & 31;
    int b0 = bg*16 + warp*2;
    const float4* xa = (const float4*)(x + (size_t)b0*REDN + idx0);
    const float4* xb = (const float4*)(x + (size_t)(b0+1)*REDN + idx0);

    float a0 = 0.f, a1 = 0.f, c0 = 0.f, c1 = 0.f;
    #pragma unroll 4
    for (int it = 0; it < 31; it++) {
        int t = lane + it*32;
        float4 xv = xa[t];
        float4 yv = xb[t];
        float4 q0 = Ms4[2*t];
        float4 q1 = Ms4[2*t + 1];
        a0 += xv.x*q0.x + xv.y*q0.z + xv.z*q1.x + xv.w*q1.z;
        a1 += xv.x*q0.y + xv.y*q0.w + xv.z*q1.y + xv.w*q1.w;
        c0 += yv.x*q0.x + yv.y*q0.z + yv.z*q1.x + yv.w*q1.z;
        c1 += yv.x*q0.y + yv.y*q0.w + yv.z*q1.y + yv.w*q1.w;
    }
    #pragma unroll
    for (int off = 16; off; off >>= 1) {
        a0 += __shfl_down_sync(0xFFFFFFFFu, a0, off);
        a1 += __shfl_down_sync(0xFFFFFFFFu, a1, off);
        c0 += __shfl_down_sync(0xFFFFFFFFu, c0, off);
        c1 += __shfl_down_sync(0xFFFFFFFFu, c1, off);
    }
    if (lane == 0) {
        atomicAdd(&out[b0*2],       a0);
        atomicAdd(&out[b0*2 + 1],   a1);
        atomicAdd(&out[(b0+1)*2],   c0);
        atomicAdd(&out[(b0+1)*2+1], c1);
    }
}

// ---------------- launcher ----------------
extern "C" void kernel_launch(void* const* d_in, const int* in_sizes, int n_in,
                              void* d_out, int out_size) {
    const float* x      = (const float*)d_in[0];
    const float* coord  = (const float*)d_in[1];
    const float* adj_w1 = (const float*)d_in[2];
    const float* adj_b1 = (const float*)d_in[3];
    const float* adj_w2 = (const float*)d_in[4];
    const float* adj_b2 = (const float*)d_in[5];
    const float* cheb_W = (const float*)d_in[6];
    const float* cheb_b = (const float*)d_in[7];
    const float* conv_w = (const float*)d_in[8];
    const float* conv_b = (const float*)d_in[9];
    const float* fc_w   = (const float*)d_in[10];
    const float* fc_b   = (const float*)d_in[11];
    float* out = (float*)d_out;

    k_adjcheb<<<1, 1024>>>(coord, adj_w1, adj_b1, adj_w2, adj_b2);
    k_Gz<<<683, 256>>>(fc_w, cheb_b, conv_w, conv_b, fc_b, out);
    dim3 gM(20, 8, 2);
    k_M<<<gM, 256>>>(cheb_W, conv_w);
    k_main<<<1024, 256>>>(x, out);
}

// round 4
// speedup vs baseline: 1.2330x; 1.2330x over previous
#include <cuda_runtime.h>

#define C     62
#define FIN   512
#define FOUT  256
#define KCH   5
#define NCLS  2
#define BATCH 2048
#define REDN  (C*FIN)     // 31744
#define CFOUT (C*FOUT)    // 15872
#define NE    (C*C)       // 3844

// ---------------- scratch (device globals, no allocation) ----------------
__device__ float d_A[NE];                         // thresholded adjacency
__device__ float d_G[NCLS*C*KCH*FOUT];            // [(n*62+i)*1280 + k*256 + f]
__device__ __align__(16) float d_Mf[REDN*NCLS];   // collapsed matrix, [(i*512+j)*2 + n]

// ---------------- 1) adjacency MLP (blocks 0-15) + const/out init (block 16) --------
__global__ void __launch_bounds__(256) k_adj(
        const float* __restrict__ coord, const float* __restrict__ w1,
        const float* __restrict__ b1, const float* __restrict__ w2,
        const float* __restrict__ b2,
        const float* __restrict__ fcw, const float* __restrict__ chebb,
        const float* __restrict__ convw, const float* __restrict__ convb,
        const float* __restrict__ fcb, float* __restrict__ out) {
    int blk = blockIdx.x;
    int tid = threadIdx.x;
    if (blk < 16) {
        int e = blk*256 + tid;
        if (e >= NE) return;
        int c1 = e / C, c2 = e % C;
        const float* cd = coord + e*4;
        float d0 = cd[0], d1 = cd[1], d2 = cd[2], d3 = cd[3];
        float acc = b2[0];
        #pragma unroll 8
        for (int h = 0; h < 64; h++) {
            float t = d0*w1[h] + d1*w1[64+h] + d2*w1[128+h] + d3*w1[192+h] + b1[h];
            acc += fmaxf(t, 0.0f) * w2[h];
        }
        d_A[e] = (c1 != c2 && acc > 0.1f) ? acc : 0.0f;
    } else {
        // const[n] = cw*sum cheb_b[f]*fcw[cf,n] + cb*sum fcw[cf,n] + fcb[n]; init out
        __shared__ float red[1024];
        __shared__ float cst[2];
        float s0 = 0.f, s1 = 0.f, t0 = 0.f, t1 = 0.f;
        for (int cf = tid; cf < CFOUT; cf += 256) {
            float w0 = fcw[cf*2], w1v = fcw[cf*2 + 1];
            float bb = chebb[cf & 255];
            s0 += w0; s1 += w1v; t0 += bb*w0; t1 += bb*w1v;
        }
        red[tid] = s0; red[256+tid] = s1; red[512+tid] = t0; red[768+tid] = t1;
        __syncthreads();
        for (int off = 128; off > 0; off >>= 1) {
            if (tid < off) {
                red[tid]     += red[tid+off];
                red[256+tid] += red[256+tid+off];
                red[512+tid] += red[512+tid+off];
                red[768+tid] += red[768+tid+off];
            }
            __syncthreads();
        }
        if (tid == 0) {
            float cw = convw[0], cb = convb[0];
            cst[0] = cw*red[512] + cb*red[0]   + fcb[0];
            cst[1] = cw*red[768] + cb*red[256] + fcb[1];
        }
        __syncthreads();
        float c0 = cst[0], c1 = cst[1];
        for (int b = tid; b < BATCH; b += 256) {
            out[b*2]     = c0;
            out[b*2 + 1] = c1;
        }
    }
}

// ---------------- 2) per-column Chebyshev recursion + G, 62 blocks ----------------
// Block i: v_k = column i of T_k.  v0 = e_i, v1 = L e_i, v_k = 2 L v_{k-1} - v_{k-2}.
// Then G[n,i,k,f] = sum_c v_k[c] * fcw[(c*256+f)*2+n].
__global__ void __launch_bounds__(256) k_chebG(const float* __restrict__ fcw) {
    __shared__ float L[C][C+1];
    __shared__ float dis[C];
    __shared__ float Tc[KCH][C];
    int i   = blockIdx.x;
    int tid = threadIdx.x;

    // load A
    for (int e = tid; e < NE; e += 256)
        L[e / C][e % C] = d_A[e];
    __syncthreads();
    // degrees
    if (tid < C) {
        float s = 0.0f;
        #pragma unroll
        for (int j = 0; j < C; j++) s += L[tid][j];
        dis[tid] = (s > 0.0f) ? (1.0f / sqrtf(s)) : 0.0f;
    }
    __syncthreads();
    // L = -D^-1/2 A D^-1/2 (in place)
    for (int e = tid; e < NE; e += 256) {
        int r = e / C, c = e % C;
        L[r][c] = -(dis[r] * L[r][c] * dis[c]);
    }
    __syncthreads();
    // column recursion
    if (tid < C) {
        Tc[0][tid] = (tid == i) ? 1.0f : 0.0f;
        Tc[1][tid] = L[tid][i];
    }
    __syncthreads();
    for (int k = 2; k < KCH; k++) {
        float v = 0.0f;
        if (tid < C) {
            float s = 0.0f;
            #pragma unroll
            for (int j = 0; j < C; j++) s += L[tid][j] * Tc[k-1][j];
            v = 2.0f*s - Tc[k-2][tid];
        }
        __syncthreads();
        if (tid < C) Tc[k][tid] = v;
        __syncthreads();
    }

    // G for this column: f = tid
    int f = tid;
    float a00=0,a01=0,a10=0,a11=0,a20=0,a21=0,a30=0,a31=0,a40=0,a41=0;
    const float2* fw2 = (const float2*)fcw;     // fw2[c*256+f] = {n0, n1}
    #pragma unroll
    for (int c = 0; c < C; c++) {
        float2 w = fw2[c*FOUT + f];
        float t0 = Tc[0][c], t1 = Tc[1][c], t2 = Tc[2][c], t3 = Tc[3][c], t4 = Tc[4][c];
        a00 += t0*w.x; a01 += t0*w.y;
        a10 += t1*w.x; a11 += t1*w.y;
        a20 += t2*w.x; a21 += t2*w.y;
        a30 += t3*w.x; a31 += t3*w.y;
        a40 += t4*w.x; a41 += t4*w.y;
    }
    float* g0 = d_G + (0*C + i)*(KCH*FOUT) + f;
    float* g1 = d_G + (1*C + i)*(KCH*FOUT) + f;
    g0[0*FOUT] = a00; g1[0*FOUT] = a01;
    g0[1*FOUT] = a10; g1[1*FOUT] = a11;
    g0[2*FOUT] = a20; g1[2*FOUT] = a21;
    g0[3*FOUT] = a30; g1[3*FOUT] = a31;
    g0[4*FOUT] = a40; g1[4*FOUT] = a41;
}

// ---------------- 3) M[n,i,j] = conv_w * sum_{kf} G[n,i,kf] * chebW[k,j,f] -----------
// Non-atomic: each block owns a 32x32 (i,j) tile for one n, full K=1280 loop.
// grid (16 j-tiles, 2 n, 2 i-tiles)
__global__ void __launch_bounds__(256) k_M(const float* __restrict__ chebW,
                                           const float* __restrict__ convw) {
    __shared__ float Gs[64][34];
    __shared__ float Ws[64][34];
    int tid   = threadIdx.x;
    int jbase = blockIdx.x * 32;
    int n     = blockIdx.y;
    int ibase = blockIdx.z * 32;

    int ty = tid >> 4, tx = tid & 15;
    int r2 = ty*2, j2 = tx*2;
    float acc00=0, acc01=0, acc10=0, acc11=0;

    int kk  = tid & 63;
    int rl0 = tid >> 6;   // 0..3

    for (int kc = 0; kc < 20; kc++) {
        int kf0 = kc*64;
        int k   = kf0 >> 8;
        int f0  = kf0 & 255;
        #pragma unroll
        for (int p = 0; p < 8; p++) {
            int r = rl0 + p*4;
            int i = ibase + r;
            Gs[kk][r] = (i < C) ? d_G[(n*C + i)*(KCH*FOUT) + kf0 + kk] : 0.0f;
            Ws[kk][r] = chebW[k*(FIN*FOUT) + (jbase + r)*FOUT + f0 + kk];
        }
        __syncthreads();
        #pragma unroll
        for (int q = 0; q < 64; q++) {
            float2 g = *(const float2*)&Gs[q][r2];
            float2 w = *(const float2*)&Ws[q][j2];
            acc00 += g.x*w.x; acc01 += g.x*w.y;
            acc10 += g.y*w.x; acc11 += g.y*w.y;
        }
        __syncthreads();
    }

    float cw = convw[0];
    int i0 = ibase + r2;
    int jj = jbase + j2;
    if (i0 < C) {
        d_Mf[(i0*FIN + jj  )*NCLS + n] = cw*acc00;
        d_Mf[(i0*FIN + jj+1)*NCLS + n] = cw*acc01;
    }
    if (i0 + 1 < C) {
        d_Mf[((i0+1)*FIN + jj  )*NCLS + n] = cw*acc10;
        d_Mf[((i0+1)*FIN + jj+1)*NCLS + n] = cw*acc11;
    }
}

// ---------------- 4) main pass: out[b,n] += sum_idx x[b,idx]*M[idx,n] ----------------
// 31 chunks of 1024 idx (8KB smem) x 128 batch-groups of 16.
__global__ void __launch_bounds__(256) k_main(const float* __restrict__ x,
                                              float* __restrict__ out) {
    __shared__ __align__(16) float4 Ms4[512];   // 1024 idx * 2 classes = 8KB
    int chunk = blockIdx.x >> 7;
    int bg    = blockIdx.x & 127;
    int idx0  = chunk * 1024;
    int tid   = threadIdx.x;

    const float4* Mf4 = (const float4*)(d_Mf + idx0*2);
    Ms4[tid]       = Mf4[tid];
    Ms4[tid + 256] = Mf4[tid + 256];
    __syncthreads();

    int warp = tid >> 5, lane = tid & 31;
    int b0 = bg*16 + warp*2;
    const float4* xa = (const float4*)(x + (size_t)b0*REDN + idx0);
    const float4* xb = (const float4*)(x + (size_t)(b0+1)*REDN + idx0);

    float a0 = 0.f, a1 = 0.f, c0 = 0.f, c1 = 0.f;
    #pragma unroll
    for (int it = 0; it < 8; it++) {
        int t = lane + it*32;
        float4 xv = xa[t];
        float4 yv = xb[t];
        float4 q0 = Ms4[2*t];
        float4 q1 = Ms4[2*t + 1];
        a0 += xv.x*q0.x + xv.y*q0.z + xv.z*q1.x + xv.w*q1.z;
        a1 += xv.x*q0.y + xv.y*q0.w + xv.z*q1.y + xv.w*q1.w;
        c0 += yv.x*q0.x + yv.y*q0.z + yv.z*q1.x + yv.w*q1.z;
        c1 += yv.x*q0.y + yv.y*q0.w + yv.z*q1.y + yv.w*q1.w;
    }
    #pragma unroll
    for (int off = 16; off; off >>= 1) {
        a0 += __shfl_down_sync(0xFFFFFFFFu, a0, off);
        a1 += __shfl_down_sync(0xFFFFFFFFu, a1, off);
        c0 += __shfl_down_sync(0xFFFFFFFFu, c0, off);
        c1 += __shfl_down_sync(0xFFFFFFFFu, c1, off);
    }
    if (lane == 0) {
        float* o0 = &out[b0*2];
        atomicAdd(o0,     a0);
        atomicAdd(o0 + 1, a1);
        atomicAdd(o0 + 2, c0);
        atomicAdd(o0 + 3, c1);
    }
}

// ---------------- launcher ----------------
extern "C" void kernel_launch(void* const* d_in, const int* in_sizes, int n_in,
                              void* d_out, int out_size) {
    const float* x      = (const float*)d_in[0];
    const float* coord  = (const float*)d_in[1];
    const float* adj_w1 = (const float*)d_in[2];
    const float* adj_b1 = (const float*)d_in[3];
    const float* adj_w2 = (const float*)d_in[4];
    const float* adj_b2 = (const float*)d_in[5];
    const float* cheb_W = (const float*)d_in[6];
    const float* cheb_b = (const float*)d_in[7];
    const float* conv_w = (const float*)d_in[8];
    const float* conv_b = (const float*)d_in[9];
    const float* fc_w   = (const float*)d_in[10];
    const float* fc_b   = (const float*)d_in[11];
    float* out = (float*)d_out;

    k_adj<<<17, 256>>>(coord, adj_w1, adj_b1, adj_w2, adj_b2,
                       fc_w, cheb_b, conv_w, conv_b, fc_b, out);
    k_chebG<<<C, 256>>>(fc_w);
    dim3 gM(16, 2, 2);
    k_M<<<gM, 256>>>(cheb_W, conv_w);
    k_main<<<3968, 256>>>(x, out);
}